// round 17
// baseline (speedup 1.0000x reference)
#include <cuda_runtime.h>

// ---- problem constants ----
#define NN        100000
#define NE        1600000
#define PER_GRAPH 100
#define N_GRAPHS  1000
#define POOL_K    30
#define C3        64
#define SCAN_BLKS ((NN + 1023) / 1024)   // 98
#define MAXDEG    96
#define XPITCH    132
#define SPLIT     50048                  // node/row split (782 gemm blocks)

using u64 = unsigned long long;
using u32 = unsigned int;

// ---- device scratch (no allocations allowed) ----
static __device__ float g_bufA[NN * 128];
static __device__ float g_bufB[NN * 128];
static __device__ float g_dinv[NN];
static __device__ int   g_count[NN];
static __device__ int   g_rowPtr[NN + 1];
static __device__ int   g_cursor[NN];
static __device__ int   g_csrSrc[NE];
static __device__ int   g_csrEid[NE];
static __device__ int   g_bsum[128];
static __device__ int   g_boff[128];
static __device__ int   g_idx64;

// ---------------- packed fp32x2 helpers (sm_103a FFMA2; IEEE .rn per lane) ----------------
__device__ __forceinline__ void ffma2(u64& d, u64 a, u64 b) {
    asm("fma.rn.f32x2 %0, %1, %2, %0;" : "+l"(d) : "l"(a), "l"(b));
}
__device__ __forceinline__ u64 dup2(float x) {
    u64 r;
    asm("mov.b64 %0, {%1, %1};" : "=l"(r) : "f"(x));
    return r;
}

// cp.async: gmem -> smem 16B (data movement only, bit-neutral)
__device__ __forceinline__ void cp_async16(u32 saddr, const void* gptr) {
    asm volatile("cp.async.cg.shared.global [%0], [%1], 16;"
                 :: "r"(saddr), "l"(gptr) : "memory");
}
__device__ __forceinline__ void cp_commit() {
    asm volatile("cp.async.commit_group;" ::: "memory");
}
__device__ __forceinline__ void cp_wait0() {
    asm volatile("cp.async.wait_group 0;" ::: "memory");
}

// ---------------- dtype probe ----------------
__global__ void k_detect(const void* __restrict__ ei) {
    if (threadIdx.x == 0 && blockIdx.x == 0) {
        const int* w = (const int*)ei;
        int is64 = 1;
        for (int i = 0; i < 64; i++)
            if (w[2 * i + 1] != 0) { is64 = 0; break; }
        g_idx64 = is64;
    }
}

__device__ __forceinline__ int edge_at(const void* p, long long i) {
    return g_idx64 ? (int)((const long long*)p)[i] : ((const int*)p)[i];
}

// ---------------- CSR build ----------------
__global__ void k_zero_counts() {
    int i = blockIdx.x * blockDim.x + threadIdx.x;
    if (i < NN) g_count[i] = 0;
}

__global__ void k_count(const void* __restrict__ ei, int e) {
    int i = blockIdx.x * blockDim.x + threadIdx.x;
    if (i >= e) return;
    int d = edge_at(ei, (long long)e + i);
    if ((unsigned)d < NN) atomicAdd(&g_count[d], 1);
}

__global__ void __launch_bounds__(1024) k_scanA() {
    __shared__ int s[1024];
    const int tid = threadIdx.x;
    const int i = blockIdx.x * 1024 + tid;
    int c = (i < NN) ? g_count[i] : 0;
    s[tid] = c;
    __syncthreads();
#pragma unroll
    for (int off = 1; off < 1024; off <<= 1) {
        int v = (tid >= off) ? s[tid - off] : 0;
        __syncthreads();
        s[tid] += v;
        __syncthreads();
    }
    if (i < NN) g_rowPtr[i] = s[tid] - c;
    if (tid == 1023) g_bsum[blockIdx.x] = s[1023];
}

__global__ void k_scanB(int nblk) {
    __shared__ int s[128];
    const int tid = threadIdx.x;
    int v = (tid < nblk) ? g_bsum[tid] : 0;
    s[tid] = v;
    __syncthreads();
#pragma unroll
    for (int off = 1; off < 128; off <<= 1) {
        int u = (tid >= off) ? s[tid - off] : 0;
        __syncthreads();
        s[tid] += u;
        __syncthreads();
    }
    if (tid < nblk) g_boff[tid] = s[tid] - v;
    if (tid == 127) g_rowPtr[NN] = s[127];
}

__global__ void k_scanC() {
    int i = blockIdx.x * blockDim.x + threadIdx.x;
    if (i >= NN) return;
    int base = g_rowPtr[i] + g_boff[i >> 10];
    g_rowPtr[i] = base;
    g_cursor[i] = base;
    float deg = (float)g_count[i] + 1.0f;
    g_dinv[i] = __fdiv_rn(1.0f, __fsqrt_rn(deg));
}

__global__ void k_fill(const void* __restrict__ ei, int e) {
    int i = blockIdx.x * blockDim.x + threadIdx.x;
    if (i >= e) return;
    int s = edge_at(ei, i);
    int d = edge_at(ei, (long long)e + i);
    if ((unsigned)s >= NN || (unsigned)d >= NN) return;
    int pos = atomicAdd(&g_cursor[d], 1);
    if ((unsigned)pos < NE) { g_csrSrc[pos] = s; g_csrEid[pos] = i; }
}

__global__ void k_sortadj() {
    int node = blockIdx.x * blockDim.x + threadIdx.x;
    if (node >= NN) return;
    int lo = g_rowPtr[node], hi = g_rowPtr[node + 1];
    int deg = hi - lo;
    if (deg <= 1) return;
    if (deg > MAXDEG) deg = MAXDEG;
    u64 v[MAXDEG];
    for (int i = 0; i < deg; i++)
        v[i] = ((u64)(unsigned)g_csrEid[lo + i] << 32) | (unsigned)g_csrSrc[lo + i];
    for (int i = 1; i < deg; i++) {
        u64 key = v[i]; int j = i - 1;
        while (j >= 0 && v[j] > key) { v[j + 1] = v[j]; j--; }
        v[j + 1] = key;
    }
    for (int i = 0; i < deg; i++)
        g_csrSrc[lo + i] = (int)(unsigned)(v[i] & 0xffffffffu);
}

// ---------------- GEMM: bufA[rows x C] = X[rows x 128] @ W[128 x C] ----------------
// 64-row tile, 128 threads, 8 rows/thread, cp.async double-buffered W.
// rowBase: tile origin (for split launches). Bit-identical fmaf chains.
template <int C, int SRC>   // SRC: 0 = param X, 1 = g_bufB
__global__ void __launch_bounds__(128, 4) k_gemm(const float* __restrict__ Xin,
                                                 const float* __restrict__ W,
                                                 int rowBase, int n) {
    __shared__ __align__(16) float xs[64 * XPITCH];
    __shared__ __align__(16) float Wsh[2][16 * C];
    const float* __restrict__ X = SRC ? (const float*)g_bufB : Xin;
    float* __restrict__ Y = g_bufA;

    const int tid = threadIdx.x;
    const int tx = tid & 15, ty = tid >> 4;
    const int row0 = rowBase + blockIdx.x * 64;
    constexpr int R   = 8;
    constexpr int CC  = C / 16;
    constexpr int CP  = CC / 2;
    constexpr int CQ  = CP / 2;
    constexpr int F4  = 4 * C;
    constexpr int PF  = F4 / 128;

    const float4* __restrict__ Wg4 = (const float4*)W;

    {
        u32 sbase = (u32)__cvta_generic_to_shared(&Wsh[0][0]);
#pragma unroll
        for (int j = 0; j < PF; j++)
            cp_async16(sbase + (tid + j * 128) * 16, Wg4 + tid + j * 128);
        cp_commit();
    }

    for (int i = tid; i < 64 * 32; i += 128) {
        int r = i >> 5, c4 = i & 31;
        float4 v = make_float4(0.f, 0.f, 0.f, 0.f);
        if (row0 + r < n) v = ((const float4*)X)[(long long)(row0 + r) * 32 + c4];
        *(float4*)&xs[r * XPITCH + c4 * 4] = v;
    }

    u64 acc[R][CP];
#pragma unroll
    for (int a = 0; a < R; a++)
#pragma unroll
        for (int b = 0; b < CP; b++) acc[a][b] = 0ull;

    cp_wait0();
    __syncthreads();

    for (int kc = 0; kc < 8; kc++) {
        const int cur = kc & 1;
        if (kc < 7) {
            u32 sbase = (u32)__cvta_generic_to_shared(&Wsh[cur ^ 1][0]);
            const float4* g = Wg4 + (long long)(kc + 1) * F4;
#pragma unroll
            for (int j = 0; j < PF; j++)
                cp_async16(sbase + (tid + j * 128) * 16, g + tid + j * 128);
            cp_commit();
        }
#pragma unroll
        for (int kq = 0; kq < 4; kq++) {
            float4 xq[R];
#pragma unroll
            for (int rr = 0; rr < R; rr++)
                xq[rr] = *(const float4*)&xs[(ty + 8 * rr) * XPITCH + kc * 16 + kq * 4];
#pragma unroll
            for (int kk = 0; kk < 4; kk++) {
                const int k = kq * 4 + kk;
                u64 wb[CP];
#pragma unroll
                for (int q = 0; q < CQ; q++) {
                    longlong2 wq = *(const longlong2*)&Wsh[cur][k * C + tx * CC + 4 * q];
                    wb[2 * q]     = (u64)wq.x;
                    wb[2 * q + 1] = (u64)wq.y;
                }
#pragma unroll
                for (int rr = 0; rr < R; rr++) {
                    u64 xa = dup2(((const float*)&xq[rr])[kk]);
#pragma unroll
                    for (int p = 0; p < CP; p++)
                        ffma2(acc[rr][p], xa, wb[p]);
                }
            }
        }
        if (kc < 7) {
            cp_wait0();
            __syncthreads();
        }
    }

    union UP { u64 u; float2 f; };
#pragma unroll
    for (int rr = 0; rr < R; rr++) {
        int row = row0 + ty + 8 * rr;
        if (row < n) {
#pragma unroll
            for (int q = 0; q < CQ; q++) {
                UP a0, a1;
                a0.u = acc[rr][2 * q];
                a1.u = acc[rr][2 * q + 1];
                float4 v = make_float4(a0.f.x, a0.f.y, a1.f.x, a1.f.y);
                ((float4*)Y)[(long long)row * (C / 4) + tx * (CC / 4) + q] = v;
            }
        }
    }
}

// ---------------- aggregation: reference-exact rounding; node range [lo,hi) ----------------
template <bool RELU>
__global__ void __launch_bounds__(256) k_agg128(const float* __restrict__ bias,
                                                int nodeLo, int nodeHi) {
    int node = nodeLo + ((blockIdx.x * 256 + threadIdx.x) >> 5);
    int lane = threadIdx.x & 31;
    if (node >= nodeHi) return;
    const float4* __restrict__ xw = (const float4*)g_bufA;
    const float d = g_dinv[node];

    float4 acc = make_float4(0.f, 0.f, 0.f, 0.f);
    int j = g_rowPtr[node];
    const int end = g_rowPtr[node + 1];
    for (; j + 1 < end; j += 2) {
        int s0 = g_csrSrc[j], s1 = g_csrSrc[j + 1];
        float nm0 = __fmul_rn(g_dinv[s0], d);
        float nm1 = __fmul_rn(g_dinv[s1], d);
        float4 v0 = xw[(long long)s0 * 32 + lane];
        float4 v1 = xw[(long long)s1 * 32 + lane];
        acc.x = __fadd_rn(acc.x, __fmul_rn(v0.x, nm0));
        acc.y = __fadd_rn(acc.y, __fmul_rn(v0.y, nm0));
        acc.z = __fadd_rn(acc.z, __fmul_rn(v0.z, nm0));
        acc.w = __fadd_rn(acc.w, __fmul_rn(v0.w, nm0));
        acc.x = __fadd_rn(acc.x, __fmul_rn(v1.x, nm1));
        acc.y = __fadd_rn(acc.y, __fmul_rn(v1.y, nm1));
        acc.z = __fadd_rn(acc.z, __fmul_rn(v1.z, nm1));
        acc.w = __fadd_rn(acc.w, __fmul_rn(v1.w, nm1));
    }
    if (j < end) {
        int s0 = g_csrSrc[j];
        float nm = __fmul_rn(g_dinv[s0], d);
        float4 v = xw[(long long)s0 * 32 + lane];
        acc.x = __fadd_rn(acc.x, __fmul_rn(v.x, nm));
        acc.y = __fadd_rn(acc.y, __fmul_rn(v.y, nm));
        acc.z = __fadd_rn(acc.z, __fmul_rn(v.z, nm));
        acc.w = __fadd_rn(acc.w, __fmul_rn(v.w, nm));
    }
    {   // self-loop last
        float dd = __fmul_rn(d, d);
        float4 v = xw[(long long)node * 32 + lane];
        acc.x = __fadd_rn(acc.x, __fmul_rn(v.x, dd));
        acc.y = __fadd_rn(acc.y, __fmul_rn(v.y, dd));
        acc.z = __fadd_rn(acc.z, __fmul_rn(v.z, dd));
        acc.w = __fadd_rn(acc.w, __fmul_rn(v.w, dd));
    }
    {   // bias last
        float4 bv = ((const float4*)bias)[lane];
        acc.x = __fadd_rn(acc.x, bv.x);
        acc.y = __fadd_rn(acc.y, bv.y);
        acc.z = __fadd_rn(acc.z, bv.z);
        acc.w = __fadd_rn(acc.w, bv.w);
    }
    if (RELU) {
        acc.x = fmaxf(acc.x, 0.f); acc.y = fmaxf(acc.y, 0.f);
        acc.z = fmaxf(acc.z, 0.f); acc.w = fmaxf(acc.w, 0.f);
    }
    ((float4*)g_bufB)[(long long)node * 32 + lane] = acc;
}

__global__ void __launch_bounds__(256) k_agg64(const float* __restrict__ bias,
                                               int nodeLo, int nodeHi) {
    int node = nodeLo + ((blockIdx.x * 256 + threadIdx.x) >> 5);
    int lane = threadIdx.x & 31;
    if (node >= nodeHi) return;
    const float2* __restrict__ xw = (const float2*)g_bufA;
    const float d = g_dinv[node];

    float2 acc = make_float2(0.f, 0.f);
    int j = g_rowPtr[node];
    const int end = g_rowPtr[node + 1];
    for (; j + 1 < end; j += 2) {
        int s0 = g_csrSrc[j], s1 = g_csrSrc[j + 1];
        float nm0 = __fmul_rn(g_dinv[s0], d);
        float nm1 = __fmul_rn(g_dinv[s1], d);
        float2 v0 = xw[(long long)s0 * 32 + lane];
        float2 v1 = xw[(long long)s1 * 32 + lane];
        acc.x = __fadd_rn(acc.x, __fmul_rn(v0.x, nm0));
        acc.y = __fadd_rn(acc.y, __fmul_rn(v0.y, nm0));
        acc.x = __fadd_rn(acc.x, __fmul_rn(v1.x, nm1));
        acc.y = __fadd_rn(acc.y, __fmul_rn(v1.y, nm1));
    }
    if (j < end) {
        int s0 = g_csrSrc[j];
        float nm = __fmul_rn(g_dinv[s0], d);
        float2 v = xw[(long long)s0 * 32 + lane];
        acc.x = __fadd_rn(acc.x, __fmul_rn(v.x, nm));
        acc.y = __fadd_rn(acc.y, __fmul_rn(v.y, nm));
    }
    {
        float dd = __fmul_rn(d, d);
        float2 v = xw[(long long)node * 32 + lane];
        acc.x = __fadd_rn(acc.x, __fmul_rn(v.x, dd));
        acc.y = __fadd_rn(acc.y, __fmul_rn(v.y, dd));
    }
    {
        float2 bv = ((const float2*)bias)[lane];
        acc.x = __fadd_rn(acc.x, bv.x);
        acc.y = __fadd_rn(acc.y, bv.y);
    }
    ((float2*)g_bufB)[(long long)node * 32 + lane] = acc;
}

// ---------------- sort pool ----------------
__global__ void k_sortpool(float* __restrict__ out) {
    __shared__ float key[PER_GRAPH];
    __shared__ int   sel[POOL_K];
    const int g = blockIdx.x;
    const int tid = threadIdx.x;
    const float* __restrict__ h = g_bufB;

    if (tid < PER_GRAPH)
        key[tid] = h[((long long)(g * PER_GRAPH + tid)) * C3 + (C3 - 1)];
    __syncthreads();

    if (tid < PER_GRAPH) {
        float ki = key[tid];
        int rank = 0;
#pragma unroll 4
        for (int j = 0; j < PER_GRAPH; j++) {
            float kj = key[j];
            rank += (kj > ki) || (kj == ki && j < tid);
        }
        if (rank < POOL_K) sel[rank] = tid;
    }
    __syncthreads();

    for (int t = tid; t < POOL_K * C3; t += blockDim.x) {
        int rank = t / C3, c = t % C3;
        int node = sel[rank];
        out[(long long)g * (POOL_K * C3) + t] =
            h[((long long)(g * PER_GRAPH + node)) * C3 + c];
    }
}

// ---------------- launch ----------------
extern "C" void kernel_launch(void* const* d_in, const int* in_sizes, int n_in,
                              void* d_out, int out_size) {
    const float* x  = (const float*)d_in[0];
    const void*  ei = d_in[1];
    const float* W1 = (const float*)d_in[3];
    const float* b1 = (const float*)d_in[4];
    const float* W2 = (const float*)d_in[5];
    const float* b2 = (const float*)d_in[6];
    const float* W3 = (const float*)d_in[7];
    const float* b3 = (const float*)d_in[8];
    float* out = (float*)d_out;

    const int n = in_sizes[0] / 128;
    const int e = in_sizes[1] / 2;
    const int T = 256;

    // split geometry
    const int gb0 = SPLIT / 64;                    // 782 gemm blocks (rows [0,SPLIT))
    const int gb1 = (n - SPLIT + 63) / 64;         // gemm blocks (rows [SPLIT,n))
    const int ab0 = (SPLIT * 32 + T - 1) / T;      // agg blocks half 0
    const int ab1 = ((NN - SPLIT) * 32 + T - 1) / T;

    cudaStream_t s2;
    cudaEvent_t evFork, evJoin, e10, e11, e2g, e20, e21, e3g;
    cudaStreamCreateWithFlags(&s2, cudaStreamNonBlocking);
    cudaEventCreateWithFlags(&evFork, cudaEventDisableTiming);
    cudaEventCreateWithFlags(&evJoin, cudaEventDisableTiming);
    cudaEventCreateWithFlags(&e10, cudaEventDisableTiming);
    cudaEventCreateWithFlags(&e11, cudaEventDisableTiming);
    cudaEventCreateWithFlags(&e2g, cudaEventDisableTiming);
    cudaEventCreateWithFlags(&e20, cudaEventDisableTiming);
    cudaEventCreateWithFlags(&e21, cudaEventDisableTiming);
    cudaEventCreateWithFlags(&e3g, cudaEventDisableTiming);

    // ---- fork: CSR build on s2, GEMM layer 1 on main ----
    cudaEventRecord(evFork, 0);
    cudaStreamWaitEvent(s2, evFork, 0);

    k_detect<<<1, 32, 0, s2>>>(ei);
    k_zero_counts<<<(NN + T - 1) / T, T, 0, s2>>>();
    k_count<<<(e + T - 1) / T, T, 0, s2>>>(ei, e);

    k_gemm<128, 0><<<(n + 63) / 64, 128>>>(x, W1, 0, n);   // launch slot 4 (ncu)

    k_scanA<<<SCAN_BLKS, 1024, 0, s2>>>();
    k_scanB<<<1, 128, 0, s2>>>(SCAN_BLKS);
    k_scanC<<<(NN + T - 1) / T, T, 0, s2>>>();
    k_fill<<<(e + T - 1) / T, T, 0, s2>>>(ei, e);
    k_sortadj<<<(NN + T - 1) / T, T, 0, s2>>>();

    cudaEventRecord(evJoin, s2);
    cudaStreamWaitEvent(0, evJoin, 0);

    // ---- layer 1 agg (halved) overlapped with layer 2 gemm halves on s2 ----
    k_agg128<true><<<ab0, T>>>(b1, 0, SPLIT);
    cudaEventRecord(e10, 0);
    k_agg128<true><<<ab1, T>>>(b1, SPLIT, NN);
    cudaEventRecord(e11, 0);

    cudaStreamWaitEvent(s2, e10, 0);
    k_gemm<128, 1><<<gb0, 128, 0, s2>>>(nullptr, W2, 0, SPLIT);
    cudaStreamWaitEvent(s2, e11, 0);
    k_gemm<128, 1><<<gb1, 128, 0, s2>>>(nullptr, W2, SPLIT, n);
    cudaEventRecord(e2g, s2);
    cudaStreamWaitEvent(0, e2g, 0);

    // ---- layer 2 agg (halved) overlapped with layer 3 gemm halves on s2 ----
    k_agg128<true><<<ab0, T>>>(b2, 0, SPLIT);
    cudaEventRecord(e20, 0);
    k_agg128<true><<<ab1, T>>>(b2, SPLIT, NN);
    cudaEventRecord(e21, 0);

    cudaStreamWaitEvent(s2, e20, 0);
    k_gemm<64, 1><<<gb0, 128, 0, s2>>>(nullptr, W3, 0, SPLIT);
    cudaStreamWaitEvent(s2, e21, 0);
    k_gemm<64, 1><<<gb1, 128, 0, s2>>>(nullptr, W3, SPLIT, n);
    cudaEventRecord(e3g, s2);
    cudaStreamWaitEvent(0, e3g, 0);

    // ---- layer 3 agg + pool ----
    k_agg64<<<(NN * 32 + T - 1) / T, T>>>(b3, 0, NN);
    k_sortpool<<<N_GRAPHS, 128>>>(out);

    cudaEventDestroy(evFork); cudaEventDestroy(evJoin);
    cudaEventDestroy(e10); cudaEventDestroy(e11); cudaEventDestroy(e2g);
    cudaEventDestroy(e20); cudaEventDestroy(e21); cudaEventDestroy(e3g);
    cudaStreamDestroy(s2);
}